// round 15
// baseline (speedup 1.0000x reference)
#include <cuda_runtime.h>
#include <cuda_bf16.h>
#include <cstdint>
#include <cstddef>

#define Bb 16
#define Nn 307
#define NSTEP 11
#define Rr (Bb*Nn)   // 4912
#define RrPad 4928
#define AGK 320
typedef unsigned long long ull;

// ---------------- device scratch (zero-initialized) ----------------
__device__ float d_A[AGK*AGK];
__device__ float d_agcW[(size_t)Nn*2*64*64];
__device__ float d_agcb[Nn*64];
__device__ float d_h[Rr*64];
__device__ float d_z[Rr*64];
__device__ float d_kh[Rr*64];
__device__ float d_kz[Rr*64];
__device__ float d_acch[Rr*64];
__device__ float d_accz[Rr*64];
__device__ float d_x1gT[(size_t)AGK*1024];
__device__ float d_yT[(size_t)Nn*1024];
__device__ __nv_bfloat16 d_x2h[(size_t)RrPad*64];
__device__ __nv_bfloat16 d_x2l[(size_t)RrPad*64];
__device__ __nv_bfloat16 d_WtHi[(size_t)4096*64];

__device__ __forceinline__ float fast_tanh(float x){
    return 1.f - __fdividef(2.f, __expf(2.f*x) + 1.f);
}
__device__ __forceinline__ unsigned smem_u32(const void* p){
    unsigned a;
    asm("{ .reg .u64 t; cvta.to.shared.u64 t, %1; cvt.u32.u64 %0, t; }" : "=r"(a) : "l"(p));
    return a;
}
#define LDSM4(r, addr) \
    asm volatile("ldmatrix.sync.aligned.m8n8.x4.shared.b16 {%0,%1,%2,%3}, [%4];" \
        : "=r"((r)[0]), "=r"((r)[1]), "=r"((r)[2]), "=r"((r)[3]) : "r"(addr))
#define MMA16816(d, a, b0v, b1v) \
    asm volatile("mma.sync.aligned.m16n8k16.row.col.f32.bf16.bf16.f32 " \
        "{%0,%1,%2,%3}, {%4,%5,%6,%7}, {%8,%9}, {%0,%1,%2,%3};" \
        : "+f"((d)[0]), "+f"((d)[1]), "+f"((d)[2]), "+f"((d)[3]) \
        : "r"((a)[0]), "r"((a)[1]), "r"((a)[2]), "r"((a)[3]), "r"(b0v), "r"(b1v))

// ---------------- k_fg1 (+ one-time precompute blocks) ----------------
#define FG1_BLKS (Rr/8)                         // 614
#define PRE_A_BLKS Nn
#define PRE_B_BLKS ((Nn*64 + 63)/64)
#define PRE_W_BLKS ((Nn*8192 + 255)/256)
#define PRE_T_BLKS 256
#define FG1_GRID_PRE (FG1_BLKS + PRE_A_BLKS + PRE_B_BLKS + PRE_W_BLKS + PRE_T_BLKS)

__global__ void __launch_bounds__(64) k_fg1(
                      const float* __restrict__ times,
                      const float* __restrict__ coeff_a,
                      const float* __restrict__ cb, const float* __restrict__ cc, const float* __restrict__ cd,
                      const float* __restrict__ hW, const float* __restrict__ hb,
                      const float* __restrict__ zW, const float* __restrict__ zb,
                      const float* __restrict__ fWin, const float* __restrict__ fbin,
                      const float* __restrict__ fWmid, const float* __restrict__ fbmid,
                      const float* __restrict__ fWout, const float* __restrict__ fbout,
                      const float* __restrict__ gWin, const float* __restrict__ gbin,
                      const float* __restrict__ gE, const float* __restrict__ gbpool,
                      const float* __restrict__ gWpool, const float* __restrict__ gWout,
                      int step, int stage){
    int t = threadIdx.x;

    if (blockIdx.x >= FG1_BLKS){
        int pb = blockIdx.x - FG1_BLKS;
        if (pb < PRE_A_BLKS){
            __shared__ float s[Nn];
            __shared__ float red[64];
            int n = pb;
            float en[8];
            #pragma unroll
            for (int d=0; d<8; d++) en[d] = gE[n*8+d];
            for (int m=t; m<Nn; m+=64){
                float acc = 0.f;
                #pragma unroll
                for (int d=0; d<8; d++) acc += en[d]*gE[m*8+d];
                s[m] = fmaxf(acc, 0.f);
            }
            __syncthreads();
            float mx = -1e30f;
            for (int m=t; m<Nn; m+=64) mx = fmaxf(mx, s[m]);
            red[t] = mx; __syncthreads();
            for (int o=32;o>0;o>>=1){ if (t<o) red[t]=fmaxf(red[t],red[t+o]); __syncthreads(); }
            mx = red[0]; __syncthreads();
            float sum = 0.f;
            for (int m=t; m<Nn; m+=64){ float e = expf(s[m]-mx); s[m]=e; sum+=e; }
            red[t]=sum; __syncthreads();
            for (int o=32;o>0;o>>=1){ if (t<o) red[t]+=red[t+o]; __syncthreads(); }
            float inv = 1.f/red[0];
            for (int m=t; m<Nn; m+=64) d_A[(size_t)n*AGK+m] = s[m]*inv;
        } else if (pb < PRE_A_BLKS + PRE_B_BLKS){
            int idx = (pb - PRE_A_BLKS)*64 + t;
            if (idx < Nn*64){
                int n = idx >> 6, o = idx & 63;
                float acc = 0.f;
                #pragma unroll
                for (int d=0; d<8; d++) acc += gE[n*8+d]*gbpool[d*64+o];
                d_agcb[idx] = acc;
            }
        } else if (pb < PRE_A_BLKS + PRE_B_BLKS + PRE_W_BLKS){
            int base = (pb - PRE_A_BLKS - PRE_B_BLKS)*256 + t*4;
            if (base < Nn*8192){
                int n = base >> 13;
                int rest = base & 8191;
                float4 acc = make_float4(0.f,0.f,0.f,0.f);
                #pragma unroll
                for (int d=0; d<8; d++){
                    float e = gE[n*8+d];
                    float4 wv = *(const float4*)&gWpool[(size_t)d*8192 + rest];
                    acc.x += e*wv.x; acc.y += e*wv.y;
                    acc.z += e*wv.z; acc.w += e*wv.w;
                }
                *(float4*)&d_agcW[base] = acc;
            }
        } else {
            int e0 = (pb - PRE_A_BLKS - PRE_B_BLKS - PRE_W_BLKS)*1024 + t;
            #pragma unroll
            for (int q=0;q<16;q++){
                int e = e0 + q*64;
                int c = e >> 6, k = e & 63;
                float wv = gWout[(size_t)k*4096 + c];
                d_WtHi[(size_t)c*64 + k] = __float2bfloat16(wv);
            }
        }
        return;
    }

    int r0 = blockIdx.x * 8;
    __shared__ float sh[8*64], sz[8*64], sx[8*64];

    float t0 = times[step], t1 = times[step+1];
    float dt = t1 - t0;
    float c  = (stage==0) ? 0.f : ((stage==3) ? dt : 0.5f*dt);
    float tv = (stage==0) ? t0  : ((stage==3) ? t1 : (t0 + 0.5f*dt));
    float w  = (stage==1 || stage==2) ? 2.f : 1.f;

    if (stage == 0){
        if (step == 0){
            float wh0 = hW[t], wh1 = hW[64+t], bh = hb[t];
            float wz0 = zW[t], wz1 = zW[64+t], bz = zb[t];
            #pragma unroll
            for (int j=0;j<8;j++){
                int r = r0+j;
                float x0 = coeff_a[(size_t)r*(NSTEP*2) + 0];
                float x1 = coeff_a[(size_t)r*(NSTEP*2) + 1];
                float hv = x0*wh0 + x1*wh1 + bh;
                float zv = x0*wz0 + x1*wz1 + bz;
                size_t base = (size_t)r*64 + t;
                d_h[base] = hv; d_z[base] = zv;
                sh[j*64+t] = hv; sz[j*64+t] = zv;
            }
        } else {
            float scp = (times[step] - times[step-1]) * (1.f/6.f);
            #pragma unroll
            for (int j=0;j<8;j++){
                size_t base = (size_t)(r0+j)*64 + t;
                float hv = d_h[base] + scp*d_acch[base];
                float zv = d_z[base] + scp*d_accz[base];
                d_h[base] = hv; d_z[base] = zv;
                sh[j*64+t] = hv; sz[j*64+t] = zv;
            }
        }
    } else {
        #pragma unroll
        for (int j=0;j<8;j++){
            size_t base = (size_t)(r0+j)*64 + t;
            sh[j*64+t] = d_h[base] + c*d_kh[base];
            sz[j*64+t] = d_z[base] + c*d_kz[base];
        }
    }
    __syncthreads();

    float af[8], ag[8];
    float bf = fbin[t], bg = gbin[t];
    #pragma unroll
    for (int j=0;j<8;j++){ af[j]=bf; ag[j]=bg; }
    #pragma unroll 8
    for (int i=0;i<64;i++){
        float wf = fWin[i*64+t];
        float wg = gWin[i*64+t];
        #pragma unroll
        for (int j=0;j<8;j++){
            af[j] = fmaf(sh[j*64+i], wf, af[j]);
            ag[j] = fmaf(sz[j*64+i], wg, ag[j]);
        }
    }
    #pragma unroll
    for (int j=0;j<8;j++){
        int r = r0+j;
        int b = r/Nn, n = r - b*Nn;
        d_x1gT[(size_t)n*1024 + b*64 + t] = fmaxf(ag[j], 0.f);
    }
    #pragma unroll
    for (int j=0;j<8;j++) sx[j*64+t] = fmaxf(af[j], 0.f);
    __syncthreads();

    float bm = fbmid[t];
    #pragma unroll
    for (int j=0;j<8;j++) af[j]=bm;
    #pragma unroll 8
    for (int i=0;i<64;i++){
        float wf = fWmid[i*64+t];
        #pragma unroll
        for (int j=0;j<8;j++) af[j] = fmaf(sx[j*64+i], wf, af[j]);
    }
    __syncthreads();
    #pragma unroll
    for (int j=0;j<8;j++) sz[j*64+t] = fmaxf(af[j], 0.f);
    __syncthreads();

    float2 b3 = ((const float2*)fbout)[t];
    float2 a3[8];
    #pragma unroll
    for (int j=0;j<8;j++) a3[j]=b3;
    #pragma unroll 8
    for (int i=0;i<64;i++){
        float2 wv = ((const float2*)fWout)[i*64 + t];
        #pragma unroll
        for (int j=0;j<8;j++){
            a3[j].x = fmaf(sz[j*64+i], wv.x, a3[j].x);
            a3[j].y = fmaf(sz[j*64+i], wv.y, a3[j].y);
        }
    }

    int idx = 0;
    #pragma unroll
    for (int jj=1; jj<=NSTEP-1; jj++) if (times[jj] <= tv) idx = jj;
    float frac = tv - times[idx];
    #pragma unroll
    for (int j=0;j<8;j++){
        size_t cbase = ((size_t)(r0+j)*NSTEP + idx)*2;
        float dX0 = cb[cbase]   + (cc[cbase]   + cd[cbase]  *frac)*frac;
        float dX1 = cb[cbase+1] + (cc[cbase+1] + cd[cbase+1]*frac)*frac;
        float dh = fast_tanh(a3[j].x)*dX0 + fast_tanh(a3[j].y)*dX1;
        size_t base = (size_t)(r0+j)*64 + t;
        d_kh[base] = dh;
        d_acch[base] = (stage==0) ? dh : (d_acch[base] + w*dh);
    }
}

// ---------------- k_agg: yT = A @ x1gT, tile 32n x 64c, grid (10,16), 128 thr ----------------
#define AGG_SMEM ((64*32*2 + 64*64)*4)   // As dup 16KB + Xs 16KB
__global__ void __launch_bounds__(128) k_agg(){
    extern __shared__ float sm[];
    float2* As2 = (float2*)sm;          // [k][32 rows] duplicated
    float*  Xs  = sm + 64*32*2;         // [k][64]
    int tid = threadIdx.x;
    int n0 = blockIdx.x * 32;
    int c0 = blockIdx.y * 64;
    int tx = tid & 31, ty = tid >> 5;   // ty: 4 groups x 8 rows

    ull acc[8];
    #pragma unroll
    for (int i=0;i<8;i++) acc[i] = 0ull;

    for (int kb = 0; kb < AGK; kb += 64){
        __syncthreads();
        #pragma unroll
        for (int it=0; it<4; it++){
            int u = it*128 + tid;            // 512 float4 = 32 rows x 64 k
            int rr = u >> 4, k4 = u & 15;
            float4 v = *(const float4*)&d_A[(size_t)(n0+rr)*AGK + kb + k4*4];
            As2[(k4*4+0)*32 + rr] = make_float2(v.x,v.x);
            As2[(k4*4+1)*32 + rr] = make_float2(v.y,v.y);
            As2[(k4*4+2)*32 + rr] = make_float2(v.z,v.z);
            As2[(k4*4+3)*32 + rr] = make_float2(v.w,v.w);
        }
        #pragma unroll
        for (int it=0; it<8; it++){
            int u = it*128 + tid;            // 1024 float4 = 64 k x 64 c
            int kk = u >> 4, c4 = u & 15;
            *(float4*)&Xs[kk*64 + c4*4] =
                *(const float4*)&d_x1gT[(size_t)(kb+kk)*1024 + c0 + c4*4];
        }
        __syncthreads();

        #pragma unroll 4
        for (int k=0;k<64;k++){
            ull b0 = *(const ull*)&Xs[k*64 + tx*2];
            const ulonglong2* Ar = (const ulonglong2*)&As2[k*32 + ty*8];
            ulonglong2 p0 = Ar[0], p1 = Ar[1], p2 = Ar[2], p3 = Ar[3];
            asm("fma.rn.f32x2 %0, %1, %2, %0;" : "+l"(acc[0]) : "l"(p0.x), "l"(b0));
            asm("fma.rn.f32x2 %0, %1, %2, %0;" : "+l"(acc[1]) : "l"(p0.y), "l"(b0));
            asm("fma.rn.f32x2 %0, %1, %2, %0;" : "+l"(acc[2]) : "l"(p1.x), "l"(b0));
            asm("fma.rn.f32x2 %0, %1, %2, %0;" : "+l"(acc[3]) : "l"(p1.y), "l"(b0));
            asm("fma.rn.f32x2 %0, %1, %2, %0;" : "+l"(acc[4]) : "l"(p2.x), "l"(b0));
            asm("fma.rn.f32x2 %0, %1, %2, %0;" : "+l"(acc[5]) : "l"(p2.y), "l"(b0));
            asm("fma.rn.f32x2 %0, %1, %2, %0;" : "+l"(acc[6]) : "l"(p3.x), "l"(b0));
            asm("fma.rn.f32x2 %0, %1, %2, %0;" : "+l"(acc[7]) : "l"(p3.y), "l"(b0));
        }
    }
    #pragma unroll
    for (int i=0;i<8;i++){
        int n = n0 + ty*8 + i;
        if (n < Nn){
            float2 v;
            asm("mov.b64 {%0,%1},%2;" : "=f"(v.x), "=f"(v.y) : "l"(acc[i]));
            *(float2*)&d_yT[(size_t)n*1024 + c0 + tx*2] = v;
        }
    }
}

// ---------------- k_x2: AGC per node, 2 blocks/node (R13 version) ----------------
__global__ void __launch_bounds__(128) k_x2(){
    __shared__ float sw0[64*32];
    __shared__ float sw1[64*32];
    __shared__ float sxs[1024];
    __shared__ float sys[1024];
    int n = blockIdx.x, half = blockIdx.y;
    int tid = threadIdx.x;
    const float4* Wg = (const float4*)&d_agcW[(size_t)n*8192];
    float4* s0 = (float4*)sw0;
    float4* s1 = (float4*)sw1;
    #pragma unroll
    for (int it=0; it<4; it++){
        int u = it*128 + tid;
        int i = u >> 3, c4 = u & 7;
        s0[u] = Wg[i*16 + half*8 + c4];
        s1[u] = Wg[1024 + i*16 + half*8 + c4];
    }
    #pragma unroll
    for (int it=0; it<2; it++){
        int u = it*128 + tid;
        ((float4*)sxs)[u] = ((const float4*)&d_x1gT[(size_t)n*1024])[u];
        ((float4*)sys)[u] = ((const float4*)&d_yT[(size_t)n*1024])[u];
    }
    __syncthreads();

    int o4 = tid & 7, b = tid >> 3;
    float4 bias = *(const float4*)&d_agcb[n*64 + half*32 + o4*4];
    ull acc0, acc1;
    asm("mov.b64 %0,{%1,%2};" : "=l"(acc0) : "f"(bias.x), "f"(bias.y));
    asm("mov.b64 %0,{%1,%2};" : "=l"(acc1) : "f"(bias.z), "f"(bias.w));
    const ull* W0p = (const ull*)sw0;
    const ull* W1p = (const ull*)sw1;
    const float* xr = &sxs[b*64];
    const float* yr = &sys[b*64];
    #pragma unroll 8
    for (int i=0;i<64;i++){
        ull w00 = W0p[i*16 + o4*2], w01 = W0p[i*16 + o4*2 + 1];
        ull w10 = W1p[i*16 + o4*2], w11 = W1p[i*16 + o4*2 + 1];
        float xv = xr[i], yv = yr[i];
        ull xx, yy;
        asm("mov.b64 %0,{%1,%1};" : "=l"(xx) : "f"(xv));
        asm("mov.b64 %0,{%1,%1};" : "=l"(yy) : "f"(yv));
        asm("fma.rn.f32x2 %0, %1, %2, %0;" : "+l"(acc0) : "l"(w00), "l"(xx));
        asm("fma.rn.f32x2 %0, %1, %2, %0;" : "+l"(acc1) : "l"(w01), "l"(xx));
        asm("fma.rn.f32x2 %0, %1, %2, %0;" : "+l"(acc0) : "l"(w10), "l"(yy));
        asm("fma.rn.f32x2 %0, %1, %2, %0;" : "+l"(acc1) : "l"(w11), "l"(yy));
    }
    float4 r;
    asm("mov.b64 {%0,%1},%2;" : "=f"(r.x), "=f"(r.y) : "l"(acc0));
    asm("mov.b64 {%0,%1},%2;" : "=f"(r.z), "=f"(r.w) : "l"(acc1));
    r.x = fmaxf(r.x,0.f); r.y = fmaxf(r.y,0.f);
    r.z = fmaxf(r.z,0.f); r.w = fmaxf(r.w,0.f);

    unsigned h01, h23;
    asm("cvt.rn.bf16x2.f32 %0, %1, %2;" : "=r"(h01) : "f"(r.y), "f"(r.x));
    asm("cvt.rn.bf16x2.f32 %0, %1, %2;" : "=r"(h23) : "f"(r.w), "f"(r.z));
    float h0 = __uint_as_float(h01 << 16);
    float h1 = __uint_as_float(h01 & 0xFFFF0000u);
    float h2 = __uint_as_float(h23 << 16);
    float h3 = __uint_as_float(h23 & 0xFFFF0000u);
    unsigned l01, l23;
    asm("cvt.rn.bf16x2.f32 %0, %1, %2;" : "=r"(l01) : "f"(r.y - h1), "f"(r.x - h0));
    asm("cvt.rn.bf16x2.f32 %0, %1, %2;" : "=r"(l23) : "f"(r.w - h3), "f"(r.z - h2));
    size_t e = ((size_t)b*Nn + n)*64 + half*32 + o4*4;
    *(uint2*)((char*)d_x2h + e*2) = make_uint2(h01, h23);
    *(uint2*)((char*)d_x2l + e*2) = make_uint2(l01, l23);
}

// ---------------- k_gz: 2-term bf16 mma.sync GEMM + tanh + contract ----------------
#define GZ_AH 0
#define GZ_AL 8192
#define GZ_BH 16384
#define GZ_SMEM_TOT 32768

__global__ void __launch_bounds__(256, 4) k_gz(
                     const float* __restrict__ gbout, int stage){
    extern __shared__ char smc[];
    unsigned sbase = smem_u32(smc);
    int tid = threadIdx.x;
    int lane = tid & 31, wid = tid >> 5;
    int r0 = blockIdx.x * 64;
    int c0 = blockIdx.y * 128;

    #pragma unroll
    for (int it=0; it<4; it++){
        int u = it*256 + tid;
        int col = u >> 3, ch = u & 7;
        unsigned dst = (unsigned)col*128u + (unsigned)((ch ^ (col & 7)) << 4);
        *(uint4*)(smc + GZ_BH + dst) =
            *(const uint4*)((const char*)d_WtHi + (size_t)(c0+col)*128 + (size_t)ch*16);
    }
    #pragma unroll
    for (int it=0; it<2; it++){
        int u = it*256 + tid;
        int row = u >> 3, ch = u & 7;
        int r = r0 + row;
        unsigned dst = (unsigned)row*128u + (unsigned)((ch ^ (row & 7)) << 4);
        *(uint4*)(smc + GZ_AH + dst) =
            *(const uint4*)((const char*)d_x2h + (size_t)r*128 + (size_t)ch*16);
        *(uint4*)(smc + GZ_AL + dst) =
            *(const uint4*)((const char*)d_x2l + (size_t)r*128 + (size_t)ch*16);
    }
    __syncthreads();

    int rowgroup = wid & 3, colgroup = wid >> 2;
    int rl = lane & 7;
    int arow = rowgroup*16 + (lane & 15);
    int aChunkHalf = (lane >> 4);
    int bcol = colgroup*64 + (lane & 7) + ((lane & 16) >> 1);
    int bChunkHalf = (lane >> 3) & 1;

    unsigned baseAH = sbase + GZ_AH + (unsigned)arow*128u;
    unsigned baseAL = sbase + GZ_AL + (unsigned)arow*128u;
    unsigned baseBH = sbase + GZ_BH + (unsigned)bcol*128u;

    float acc[8][4];
    #pragma unroll
    for (int i=0;i<8;i++){
        acc[i][0]=0.f; acc[i][1]=0.f; acc[i][2]=0.f; acc[i][3]=0.f;
    }

    #pragma unroll
    for (int ks=0; ks<4; ks++){
        int chA = ks*2 + aChunkHalf;
        unsigned asw = (unsigned)((chA ^ rl) << 4);
        unsigned afH[4], afL[4];
        LDSM4(afH, baseAH + asw);
        LDSM4(afL, baseAL + asw);
        int chB = ks*2 + bChunkHalf;
        unsigned bsw = (unsigned)((chB ^ rl) << 4);
        #pragma unroll
        for (int ng2=0; ng2<4; ng2++){
            unsigned bH[4];
            LDSM4(bH, baseBH + (unsigned)ng2*2048u + bsw);
            MMA16816(acc[ng2*2],   afH, bH[0], bH[1]);
            MMA16816(acc[ng2*2+1], afH, bH[2], bH[3]);
            MMA16816(acc[ng2*2],   afL, bH[0], bH[1]);
            MMA16816(acc[ng2*2+1], afL, bH[2], bH[3]);
        }
    }

    int g = rowgroup*16 + (lane >> 2);
    int rA = r0 + g, rB = rA + 8;
    int t2 = (lane & 3)*2;
    bool okA = rA < Rr, okB = rB < Rr;
    float wrk = (stage==1 || stage==2) ? 2.f : 1.f;
    float sA = 0.f, sB = 0.f;
    #pragma unroll
    for (int ng8=0; ng8<8; ng8++){
        int j = ng8*8 + t2;
        int colg = colgroup*64 + j;
        float2 bias = *(const float2*)&gbout[c0 + colg];
        float2 dhA = okA ? *(const float2*)&d_kh[(size_t)rA*64 + j] : make_float2(0.f,0.f);
        float2 dhB = okB ? *(const float2*)&d_kh[(size_t)rB*64 + j] : make_float2(0.f,0.f);
        sA += fast_tanh(acc[ng8][0] + bias.x)*dhA.x + fast_tanh(acc[ng8][1] + bias.y)*dhA.y;
        sB += fast_tanh(acc[ng8][2] + bias.x)*dhB.x + fast_tanh(acc[ng8][3] + bias.y)*dhB.y;
    }
    #pragma unroll
    for (int d=1; d<4; d<<=1){
        sA += __shfl_xor_sync(0xffffffffu, sA, d);
        sB += __shfl_xor_sync(0xffffffffu, sB, d);
    }
    if ((lane & 3) == 0){
        int i0 = blockIdx.y*2 + colgroup;
        if (okA){
            size_t o = (size_t)rA*64 + i0;
            d_kz[o] = sA;
            d_accz[o] = (stage==0) ? sA : (d_accz[o] + wrk*sA);
        }
        if (okB){
            size_t o = (size_t)rB*64 + i0;
            d_kz[o] = sB;
            d_accz[o] = (stage==0) ? sB : (d_accz[o] + wrk*sB);
        }
    }
}

// ---------------- k_out ----------------
__global__ void k_out(const float* __restrict__ convW, const float* __restrict__ convb,
                      const float* __restrict__ times, float* __restrict__ out){
    __shared__ float szr[64];
    int r = blockIdx.x, t = threadIdx.x;
    float sc = (times[NSTEP] - times[NSTEP-1]) * (1.f/6.f);
    size_t base = (size_t)r*64 + t;
    szr[t] = d_z[base] + sc*d_accz[base];
    __syncthreads();
    if (t < 12){
        float acc = convb[t];
        #pragma unroll 8
        for (int h=0; h<64; h++) acc = fmaf(szr[h], convW[t*64+h], acc);
        int b = r / Nn, n = r - b*Nn;
        out[(size_t)(b*12 + t)*Nn + n] = acc;
    }
}

// ---------------- launcher ----------------
extern "C" void kernel_launch(void* const* d_in, const int* in_sizes, int n_in,
                              void* d_out, int out_size){
    const float* coeff_a = (const float*)d_in[0];
    const float* coeff_b = (const float*)d_in[1];
    const float* coeff_c = (const float*)d_in[2];
    const float* coeff_d = (const float*)d_in[3];
    const float* times   = (const float*)d_in[4];
    const float* h_W     = (const float*)d_in[5];
    const float* h_b     = (const float*)d_in[6];
    const float* z_W     = (const float*)d_in[7];
    const float* z_b     = (const float*)d_in[8];
    const float* f_W_in  = (const float*)d_in[9];
    const float* f_b_in  = (const float*)d_in[10];
    const float* f_W_mid = (const float*)d_in[11];
    const float* f_b_mid = (const float*)d_in[12];
    const float* f_W_out = (const float*)d_in[13];
    const float* f_b_out = (const float*)d_in[14];
    const float* g_W_in  = (const float*)d_in[15];
    const float* g_b_in  = (const float*)d_in[16];
    const float* g_E     = (const float*)d_in[17];
    const float* g_Wpool = (const float*)d_in[18];
    const float* g_bpool = (const float*)d_in[19];
    const float* g_W_out = (const float*)d_in[20];
    const float* g_b_out = (const float*)d_in[21];
    const float* conv_W  = (const float*)d_in[22];
    const float* conv_b  = (const float*)d_in[23];
    float* out = (float*)d_out;

    cudaFuncSetAttribute(k_agg, cudaFuncAttributeMaxDynamicSharedMemorySize, AGG_SMEM);
    cudaFuncSetAttribute(k_gz,  cudaFuncAttributeMaxDynamicSharedMemorySize, GZ_SMEM_TOT);

    for (int step = 0; step < NSTEP; step++){
        for (int stage = 0; stage < 4; stage++){
            int grid = (step==0 && stage==0) ? FG1_GRID_PRE : FG1_BLKS;
            k_fg1<<<grid, 64>>>(times, coeff_a, coeff_b, coeff_c, coeff_d,
                                h_W, h_b, z_W, z_b,
                                f_W_in, f_b_in, f_W_mid, f_b_mid, f_W_out, f_b_out,
                                g_W_in, g_b_in, g_E, g_bpool, g_Wpool, g_W_out,
                                step, stage);
            k_agg<<<dim3(10,16), 128, AGG_SMEM>>>();
            k_x2<<<dim3(Nn,2), 128>>>();
            k_gz<<<dim3(77,32), 256, GZ_SMEM_TOT>>>(g_b_out, stage);
        }
    }
    k_out<<<Rr, 64>>>(conv_W, conv_b, times, out);
}

// round 16
// speedup vs baseline: 1.0747x; 1.0747x over previous
#include <cuda_runtime.h>
#include <cuda_bf16.h>
#include <cstdint>
#include <cstddef>

#define Bb 16
#define Nn 307
#define NSTEP 11
#define Rr (Bb*Nn)   // 4912
#define RrPad 4928
#define AGK 320
typedef unsigned long long ull;

// ---------------- device scratch (zero-initialized) ----------------
__device__ float d_A[AGK*AGK];
__device__ float d_agcW[(size_t)Nn*2*64*64];
__device__ float d_agcb[Nn*64];
__device__ float d_h[Rr*64];
__device__ float d_z[Rr*64];
__device__ float d_kh[Rr*64];
__device__ float d_kz[Rr*64];
__device__ float d_acch[Rr*64];
__device__ float d_accz[Rr*64];
__device__ float d_x1gT[(size_t)AGK*1024];
__device__ float d_yT[(size_t)Nn*1024];
__device__ __nv_bfloat16 d_x2h[(size_t)RrPad*64];
__device__ __nv_bfloat16 d_x2l[(size_t)RrPad*64];
__device__ __nv_bfloat16 d_WtHi[(size_t)4096*64];

__device__ __forceinline__ float fast_tanh(float x){
    return 1.f - __fdividef(2.f, __expf(2.f*x) + 1.f);
}
__device__ __forceinline__ unsigned smem_u32(const void* p){
    unsigned a;
    asm("{ .reg .u64 t; cvta.to.shared.u64 t, %1; cvt.u32.u64 %0, t; }" : "=r"(a) : "l"(p));
    return a;
}
#define LDSM4(r, addr) \
    asm volatile("ldmatrix.sync.aligned.m8n8.x4.shared.b16 {%0,%1,%2,%3}, [%4];" \
        : "=r"((r)[0]), "=r"((r)[1]), "=r"((r)[2]), "=r"((r)[3]) : "r"(addr))
#define MMA16816(d, a, b0v, b1v) \
    asm volatile("mma.sync.aligned.m16n8k16.row.col.f32.bf16.bf16.f32 " \
        "{%0,%1,%2,%3}, {%4,%5,%6,%7}, {%8,%9}, {%0,%1,%2,%3};" \
        : "+f"((d)[0]), "+f"((d)[1]), "+f"((d)[2]), "+f"((d)[3]) \
        : "r"((a)[0]), "r"((a)[1]), "r"((a)[2]), "r"((a)[3]), "r"(b0v), "r"(b1v))

// ---------------- k_fg1 (+ one-time precompute blocks) — R13 exact ----------------
#define FG1_BLKS (Rr/8)                         // 614
#define PRE_A_BLKS Nn
#define PRE_B_BLKS ((Nn*64 + 63)/64)
#define PRE_W_BLKS ((Nn*8192 + 255)/256)
#define PRE_T_BLKS 256
#define FG1_GRID_PRE (FG1_BLKS + PRE_A_BLKS + PRE_B_BLKS + PRE_W_BLKS + PRE_T_BLKS)

__global__ void __launch_bounds__(64) k_fg1(
                      const float* __restrict__ times,
                      const float* __restrict__ coeff_a,
                      const float* __restrict__ cb, const float* __restrict__ cc, const float* __restrict__ cd,
                      const float* __restrict__ hW, const float* __restrict__ hb,
                      const float* __restrict__ zW, const float* __restrict__ zb,
                      const float* __restrict__ fWin, const float* __restrict__ fbin,
                      const float* __restrict__ fWmid, const float* __restrict__ fbmid,
                      const float* __restrict__ fWout, const float* __restrict__ fbout,
                      const float* __restrict__ gWin, const float* __restrict__ gbin,
                      const float* __restrict__ gE, const float* __restrict__ gbpool,
                      const float* __restrict__ gWpool, const float* __restrict__ gWout,
                      int step, int stage){
    int t = threadIdx.x;

    if (blockIdx.x >= FG1_BLKS){
        int pb = blockIdx.x - FG1_BLKS;
        if (pb < PRE_A_BLKS){
            __shared__ float s[Nn];
            __shared__ float red[64];
            int n = pb;
            float en[8];
            #pragma unroll
            for (int d=0; d<8; d++) en[d] = gE[n*8+d];
            for (int m=t; m<Nn; m+=64){
                float acc = 0.f;
                #pragma unroll
                for (int d=0; d<8; d++) acc += en[d]*gE[m*8+d];
                s[m] = fmaxf(acc, 0.f);
            }
            __syncthreads();
            float mx = -1e30f;
            for (int m=t; m<Nn; m+=64) mx = fmaxf(mx, s[m]);
            red[t] = mx; __syncthreads();
            for (int o=32;o>0;o>>=1){ if (t<o) red[t]=fmaxf(red[t],red[t+o]); __syncthreads(); }
            mx = red[0]; __syncthreads();
            float sum = 0.f;
            for (int m=t; m<Nn; m+=64){ float e = expf(s[m]-mx); s[m]=e; sum+=e; }
            red[t]=sum; __syncthreads();
            for (int o=32;o>0;o>>=1){ if (t<o) red[t]+=red[t+o]; __syncthreads(); }
            float inv = 1.f/red[0];
            for (int m=t; m<Nn; m+=64) d_A[(size_t)n*AGK+m] = s[m]*inv;
        } else if (pb < PRE_A_BLKS + PRE_B_BLKS){
            int idx = (pb - PRE_A_BLKS)*64 + t;
            if (idx < Nn*64){
                int n = idx >> 6, o = idx & 63;
                float acc = 0.f;
                #pragma unroll
                for (int d=0; d<8; d++) acc += gE[n*8+d]*gbpool[d*64+o];
                d_agcb[idx] = acc;
            }
        } else if (pb < PRE_A_BLKS + PRE_B_BLKS + PRE_W_BLKS){
            int base = (pb - PRE_A_BLKS - PRE_B_BLKS)*256 + t*4;
            if (base < Nn*8192){
                int n = base >> 13;
                int rest = base & 8191;
                float4 acc = make_float4(0.f,0.f,0.f,0.f);
                #pragma unroll
                for (int d=0; d<8; d++){
                    float e = gE[n*8+d];
                    float4 wv = *(const float4*)&gWpool[(size_t)d*8192 + rest];
                    acc.x += e*wv.x; acc.y += e*wv.y;
                    acc.z += e*wv.z; acc.w += e*wv.w;
                }
                *(float4*)&d_agcW[base] = acc;
            }
        } else {
            int e0 = (pb - PRE_A_BLKS - PRE_B_BLKS - PRE_W_BLKS)*1024 + t;
            #pragma unroll
            for (int q=0;q<16;q++){
                int e = e0 + q*64;
                int c = e >> 6, k = e & 63;
                float wv = gWout[(size_t)k*4096 + c];
                d_WtHi[(size_t)c*64 + k] = __float2bfloat16(wv);
            }
        }
        return;
    }

    int r0 = blockIdx.x * 8;
    __shared__ float sh[8*64], sz[8*64], sx[8*64];

    float t0 = times[step], t1 = times[step+1];
    float dt = t1 - t0;
    float c  = (stage==0) ? 0.f : ((stage==3) ? dt : 0.5f*dt);
    float tv = (stage==0) ? t0  : ((stage==3) ? t1 : (t0 + 0.5f*dt));
    float w  = (stage==1 || stage==2) ? 2.f : 1.f;

    if (stage == 0){
        if (step == 0){
            float wh0 = hW[t], wh1 = hW[64+t], bh = hb[t];
            float wz0 = zW[t], wz1 = zW[64+t], bz = zb[t];
            #pragma unroll
            for (int j=0;j<8;j++){
                int r = r0+j;
                float x0 = coeff_a[(size_t)r*(NSTEP*2) + 0];
                float x1 = coeff_a[(size_t)r*(NSTEP*2) + 1];
                float hv = x0*wh0 + x1*wh1 + bh;
                float zv = x0*wz0 + x1*wz1 + bz;
                size_t base = (size_t)r*64 + t;
                d_h[base] = hv; d_z[base] = zv;
                sh[j*64+t] = hv; sz[j*64+t] = zv;
            }
        } else {
            float scp = (times[step] - times[step-1]) * (1.f/6.f);
            #pragma unroll
            for (int j=0;j<8;j++){
                size_t base = (size_t)(r0+j)*64 + t;
                float hv = d_h[base] + scp*d_acch[base];
                float zv = d_z[base] + scp*d_accz[base];
                d_h[base] = hv; d_z[base] = zv;
                sh[j*64+t] = hv; sz[j*64+t] = zv;
            }
        }
    } else {
        #pragma unroll
        for (int j=0;j<8;j++){
            size_t base = (size_t)(r0+j)*64 + t;
            sh[j*64+t] = d_h[base] + c*d_kh[base];
            sz[j*64+t] = d_z[base] + c*d_kz[base];
        }
    }
    __syncthreads();

    float af[8], ag[8];
    float bf = fbin[t], bg = gbin[t];
    #pragma unroll
    for (int j=0;j<8;j++){ af[j]=bf; ag[j]=bg; }
    #pragma unroll 8
    for (int i=0;i<64;i++){
        float wf = fWin[i*64+t];
        float wg = gWin[i*64+t];
        #pragma unroll
        for (int j=0;j<8;j++){
            af[j] = fmaf(sh[j*64+i], wf, af[j]);
            ag[j] = fmaf(sz[j*64+i], wg, ag[j]);
        }
    }
    #pragma unroll
    for (int j=0;j<8;j++){
        int r = r0+j;
        int b = r/Nn, n = r - b*Nn;
        d_x1gT[(size_t)n*1024 + b*64 + t] = fmaxf(ag[j], 0.f);
    }
    #pragma unroll
    for (int j=0;j<8;j++) sx[j*64+t] = fmaxf(af[j], 0.f);
    __syncthreads();

    float bm = fbmid[t];
    #pragma unroll
    for (int j=0;j<8;j++) af[j]=bm;
    #pragma unroll 8
    for (int i=0;i<64;i++){
        float wf = fWmid[i*64+t];
        #pragma unroll
        for (int j=0;j<8;j++) af[j] = fmaf(sx[j*64+i], wf, af[j]);
    }
    __syncthreads();
    #pragma unroll
    for (int j=0;j<8;j++) sz[j*64+t] = fmaxf(af[j], 0.f);
    __syncthreads();

    float2 b3 = ((const float2*)fbout)[t];
    float2 a3[8];
    #pragma unroll
    for (int j=0;j<8;j++) a3[j]=b3;
    #pragma unroll 8
    for (int i=0;i<64;i++){
        float2 wv = ((const float2*)fWout)[i*64 + t];
        #pragma unroll
        for (int j=0;j<8;j++){
            a3[j].x = fmaf(sz[j*64+i], wv.x, a3[j].x);
            a3[j].y = fmaf(sz[j*64+i], wv.y, a3[j].y);
        }
    }

    int idx = 0;
    #pragma unroll
    for (int jj=1; jj<=NSTEP-1; jj++) if (times[jj] <= tv) idx = jj;
    float frac = tv - times[idx];
    #pragma unroll
    for (int j=0;j<8;j++){
        size_t cbase = ((size_t)(r0+j)*NSTEP + idx)*2;
        float dX0 = cb[cbase]   + (cc[cbase]   + cd[cbase]  *frac)*frac;
        float dX1 = cb[cbase+1] + (cc[cbase+1] + cd[cbase+1]*frac)*frac;
        float dh = fast_tanh(a3[j].x)*dX0 + fast_tanh(a3[j].y)*dX1;
        size_t base = (size_t)(r0+j)*64 + t;
        d_kh[base] = dh;
        d_acch[base] = (stage==0) ? dh : (d_acch[base] + w*dh);
    }
}

// ---------------- k_agg — R13 exact (32x128 tiles, grid (10,8), 256 thr) ----------------
#define AGG_SMEM ((64*32*2 + 64*128)*4)
__global__ void __launch_bounds__(256) k_agg(){
    extern __shared__ float sm[];
    float2* As2 = (float2*)sm;
    float*  Xs  = sm + 64*32*2;
    int tid = threadIdx.x;
    int n0 = blockIdx.x * 32;
    int c0 = blockIdx.y * 128;
    int tx = tid & 31, ty = tid >> 5;

    ull acc[4][2];
    #pragma unroll
    for (int i=0;i<4;i++){ acc[i][0]=0ull; acc[i][1]=0ull; }

    for (int kb = 0; kb < AGK; kb += 64){
        __syncthreads();
        #pragma unroll
        for (int it=0; it<2; it++){
            int u = it*256 + tid;
            int rr = u >> 4, k4 = u & 15;
            float4 v = *(const float4*)&d_A[(size_t)(n0+rr)*AGK + kb + k4*4];
            As2[(k4*4+0)*32 + rr] = make_float2(v.x,v.x);
            As2[(k4*4+1)*32 + rr] = make_float2(v.y,v.y);
            As2[(k4*4+2)*32 + rr] = make_float2(v.z,v.z);
            As2[(k4*4+3)*32 + rr] = make_float2(v.w,v.w);
        }
        #pragma unroll
        for (int it=0; it<8; it++){
            int u = it*256 + tid;
            int kk = u >> 5, c4 = u & 31;
            *(float4*)&Xs[kk*128 + c4*4] =
                *(const float4*)&d_x1gT[(size_t)(kb+kk)*1024 + c0 + c4*4];
        }
        __syncthreads();

        #pragma unroll 4
        for (int k=0;k<64;k++){
            ulonglong2 bv = *(const ulonglong2*)&Xs[k*128 + tx*4];
            ull b0 = bv.x, b1 = bv.y;
            const ulonglong2* Ar = (const ulonglong2*)&As2[k*32 + ty*4];
            ulonglong2 p0 = Ar[0], p1 = Ar[1];
            asm("fma.rn.f32x2 %0, %1, %2, %0;" : "+l"(acc[0][0]) : "l"(p0.x), "l"(b0));
            asm("fma.rn.f32x2 %0, %1, %2, %0;" : "+l"(acc[0][1]) : "l"(p0.x), "l"(b1));
            asm("fma.rn.f32x2 %0, %1, %2, %0;" : "+l"(acc[1][0]) : "l"(p0.y), "l"(b0));
            asm("fma.rn.f32x2 %0, %1, %2, %0;" : "+l"(acc[1][1]) : "l"(p0.y), "l"(b1));
            asm("fma.rn.f32x2 %0, %1, %2, %0;" : "+l"(acc[2][0]) : "l"(p1.x), "l"(b0));
            asm("fma.rn.f32x2 %0, %1, %2, %0;" : "+l"(acc[2][1]) : "l"(p1.x), "l"(b1));
            asm("fma.rn.f32x2 %0, %1, %2, %0;" : "+l"(acc[3][0]) : "l"(p1.y), "l"(b0));
            asm("fma.rn.f32x2 %0, %1, %2, %0;" : "+l"(acc[3][1]) : "l"(p1.y), "l"(b1));
        }
    }
    #pragma unroll
    for (int i=0;i<4;i++){
        int n = n0 + ty*4 + i;
        if (n < Nn){
            float4 v;
            asm("mov.b64 {%0,%1},%2;" : "=f"(v.x), "=f"(v.y) : "l"(acc[i][0]));
            asm("mov.b64 {%0,%1},%2;" : "=f"(v.z), "=f"(v.w) : "l"(acc[i][1]));
            *(float4*)&d_yT[(size_t)n*1024 + c0 + tx*4] = v;
        }
    }
}

// ---------------- k_x2: (Nn,2) grid, NOW 256 threads (thread = o-pair x batch) ----------------
__global__ void __launch_bounds__(256) k_x2(){
    __shared__ float sw0[64*32];
    __shared__ float sw1[64*32];
    __shared__ float sxs[1024];
    __shared__ float sys[1024];
    int n = blockIdx.x, half = blockIdx.y;
    int tid = threadIdx.x;
    const float4* Wg = (const float4*)&d_agcW[(size_t)n*8192];
    float4* s0 = (float4*)sw0;
    float4* s1 = (float4*)sw1;
    #pragma unroll
    for (int it=0; it<2; it++){
        int u = it*256 + tid;            // 512 float4 per W half
        int i = u >> 3, c4 = u & 7;
        s0[u] = Wg[i*16 + half*8 + c4];
        s1[u] = Wg[1024 + i*16 + half*8 + c4];
    }
    {
        ((float4*)sxs)[tid] = ((const float4*)&d_x1gT[(size_t)n*1024])[tid];
        ((float4*)sys)[tid] = ((const float4*)&d_yT[(size_t)n*1024])[tid];
    }
    __syncthreads();

    int o2 = tid & 15, b = tid >> 4;     // 16 o-pairs x 16 batches
    float2 bias = *(const float2*)&d_agcb[n*64 + half*32 + o2*2];
    ull acc0;
    asm("mov.b64 %0,{%1,%2};" : "=l"(acc0) : "f"(bias.x), "f"(bias.y));
    const ull* W0p = (const ull*)sw0;    // [i*16 + o2]
    const ull* W1p = (const ull*)sw1;
    const float* xr = &sxs[b*64];
    const float* yr = &sys[b*64];
    #pragma unroll 8
    for (int i=0;i<64;i++){
        ull w0 = W0p[i*16 + o2];
        ull w1 = W1p[i*16 + o2];
        float xv = xr[i], yv = yr[i];
        ull xx, yy;
        asm("mov.b64 %0,{%1,%1};" : "=l"(xx) : "f"(xv));
        asm("mov.b64 %0,{%1,%1};" : "=l"(yy) : "f"(yv));
        asm("fma.rn.f32x2 %0, %1, %2, %0;" : "+l"(acc0) : "l"(w0), "l"(xx));
        asm("fma.rn.f32x2 %0, %1, %2, %0;" : "+l"(acc0) : "l"(w1), "l"(yy));
    }
    float2 r;
    asm("mov.b64 {%0,%1},%2;" : "=f"(r.x), "=f"(r.y) : "l"(acc0));
    r.x = fmaxf(r.x,0.f); r.y = fmaxf(r.y,0.f);

    unsigned h01;
    asm("cvt.rn.bf16x2.f32 %0, %1, %2;" : "=r"(h01) : "f"(r.y), "f"(r.x));
    float h0 = __uint_as_float(h01 << 16);
    float h1 = __uint_as_float(h01 & 0xFFFF0000u);
    unsigned l01;
    asm("cvt.rn.bf16x2.f32 %0, %1, %2;" : "=r"(l01) : "f"(r.y - h1), "f"(r.x - h0));
    size_t e = ((size_t)b*Nn + n)*64 + half*32 + o2*2;
    *(unsigned*)((char*)d_x2h + e*2) = h01;
    *(unsigned*)((char*)d_x2l + e*2) = l01;
}

// ---------------- k_gz — R13 exact (2-term bf16 mma.sync) ----------------
#define GZ_AH 0
#define GZ_AL 8192
#define GZ_BH 16384
#define GZ_SMEM_TOT 32768

__global__ void __launch_bounds__(256, 4) k_gz(
                     const float* __restrict__ gbout, int stage){
    extern __shared__ char smc[];
    unsigned sbase = smem_u32(smc);
    int tid = threadIdx.x;
    int lane = tid & 31, wid = tid >> 5;
    int r0 = blockIdx.x * 64;
    int c0 = blockIdx.y * 128;

    #pragma unroll
    for (int it=0; it<4; it++){
        int u = it*256 + tid;
        int col = u >> 3, ch = u & 7;
        unsigned dst = (unsigned)col*128u + (unsigned)((ch ^ (col & 7)) << 4);
        *(uint4*)(smc + GZ_BH + dst) =
            *(const uint4*)((const char*)d_WtHi + (size_t)(c0+col)*128 + (size_t)ch*16);
    }
    #pragma unroll
    for (int it=0; it<2; it++){
        int u = it*256 + tid;
        int row = u >> 3, ch = u & 7;
        int r = r0 + row;
        unsigned dst = (unsigned)row*128u + (unsigned)((ch ^ (row & 7)) << 4);
        *(uint4*)(smc + GZ_AH + dst) =
            *(const uint4*)((const char*)d_x2h + (size_t)r*128 + (size_t)ch*16);
        *(uint4*)(smc + GZ_AL + dst) =
            *(const uint4*)((const char*)d_x2l + (size_t)r*128 + (size_t)ch*16);
    }
    __syncthreads();

    int rowgroup = wid & 3, colgroup = wid >> 2;
    int rl = lane & 7;
    int arow = rowgroup*16 + (lane & 15);
    int aChunkHalf = (lane >> 4);
    int bcol = colgroup*64 + (lane & 7) + ((lane & 16) >> 1);
    int bChunkHalf = (lane >> 3) & 1;

    unsigned baseAH = sbase + GZ_AH + (unsigned)arow*128u;
    unsigned baseAL = sbase + GZ_AL + (unsigned)arow*128u;
    unsigned baseBH = sbase + GZ_BH + (unsigned)bcol*128u;

    float acc[8][4];
    #pragma unroll
    for (int i=0;i<8;i++){
        acc[i][0]=0.f; acc[i][1]=0.f; acc[i][2]=0.f; acc[i][3]=0.f;
    }

    #pragma unroll
    for (int ks=0; ks<4; ks++){
        int chA = ks*2 + aChunkHalf;
        unsigned asw = (unsigned)((chA ^ rl) << 4);
        unsigned afH[4], afL[4];
        LDSM4(afH, baseAH + asw);
        LDSM4(afL, baseAL + asw);
        int chB = ks*2 + bChunkHalf;
        unsigned bsw = (unsigned)((chB ^ rl) << 4);
        #pragma unroll
        for (int ng2=0; ng2<4; ng2++){
            unsigned bH[4];
            LDSM4(bH, baseBH + (unsigned)ng2*2048u + bsw);
            MMA16816(acc[ng2*2],   afH, bH[0], bH[1]);
            MMA16816(acc[ng2*2+1], afH, bH[2], bH[3]);
            MMA16816(acc[ng2*2],   afL, bH[0], bH[1]);
            MMA16816(acc[ng2*2+1], afL, bH[2], bH[3]);
        }
    }

    int g = rowgroup*16 + (lane >> 2);
    int rA = r0 + g, rB = rA + 8;
    int t2 = (lane & 3)*2;
    bool okA = rA < Rr, okB = rB < Rr;
    float wrk = (stage==1 || stage==2) ? 2.f : 1.f;
    float sA = 0.f, sB = 0.f;
    #pragma unroll
    for (int ng8=0; ng8<8; ng8++){
        int j = ng8*8 + t2;
        int colg = colgroup*64 + j;
        float2 bias = *(const float2*)&gbout[c0 + colg];
        float2 dhA = okA ? *(const float2*)&d_kh[(size_t)rA*64 + j] : make_float2(0.f,0.f);
        float2 dhB = okB ? *(const float2*)&d_kh[(size_t)rB*64 + j] : make_float2(0.f,0.f);
        sA += fast_tanh(acc[ng8][0] + bias.x)*dhA.x + fast_tanh(acc[ng8][1] + bias.y)*dhA.y;
        sB += fast_tanh(acc[ng8][2] + bias.x)*dhB.x + fast_tanh(acc[ng8][3] + bias.y)*dhB.y;
    }
    #pragma unroll
    for (int d=1; d<4; d<<=1){
        sA += __shfl_xor_sync(0xffffffffu, sA, d);
        sB += __shfl_xor_sync(0xffffffffu, sB, d);
    }
    if ((lane & 3) == 0){
        int i0 = blockIdx.y*2 + colgroup;
        if (okA){
            size_t o = (size_t)rA*64 + i0;
            d_kz[o] = sA;
            d_accz[o] = (stage==0) ? sA : (d_accz[o] + wrk*sA);
        }
        if (okB){
            size_t o = (size_t)rB*64 + i0;
            d_kz[o] = sB;
            d_accz[o] = (stage==0) ? sB : (d_accz[o] + wrk*sB);
        }
    }
}

// ---------------- k_out ----------------
__global__ void k_out(const float* __restrict__ convW, const float* __restrict__ convb,
                      const float* __restrict__ times, float* __restrict__ out){
    __shared__ float szr[64];
    int r = blockIdx.x, t = threadIdx.x;
    float sc = (times[NSTEP] - times[NSTEP-1]) * (1.f/6.f);
    size_t base = (size_t)r*64 + t;
    szr[t] = d_z[base] + sc*d_accz[base];
    __syncthreads();
    if (t < 12){
        float acc = convb[t];
        #pragma unroll 8
        for (int h=0; h<64; h++) acc = fmaf(szr[h], convW[t*64+h], acc);
        int b = r / Nn, n = r - b*Nn;
        out[(size_t)(b*12 + t)*Nn + n] = acc;
    }
}

// ---------------- launcher ----------------
extern "C" void kernel_launch(void* const* d_in, const int* in_sizes, int n_in,
                              void* d_out, int out_size){
    const float* coeff_a = (const float*)d_in[0];
    const float* coeff_b = (const float*)d_in[1];
    const float* coeff_c = (const float*)d_in[2];
    const float* coeff_d = (const float*)d_in[3];
    const float* times   = (const float*)d_in[4];
    const float* h_W     = (const float*)d_in[5];
    const float* h_b     = (const float*)d_in[6];
    const float* z_W     = (const float*)d_in[7];
    const float* z_b     = (const float*)d_in[8];
    const float* f_W_in  = (const float*)d_in[9];
    const float* f_b_in  = (const float*)d_in[10];
    const float* f_W_mid = (const float*)d_in[11];
    const float* f_b_mid = (const float*)d_in[12];
    const float* f_W_out = (const float*)d_in[13];
    const float* f_b_out = (const float*)d_in[14];
    const float* g_W_in  = (const float*)d_in[15];
    const float* g_b_in  = (const float*)d_in[16];
    const float* g_E     = (const float*)d_in[17];
    const float* g_Wpool = (const float*)d_in[18];
    const float* g_bpool = (const float*)d_in[19];
    const float* g_W_out = (const float*)d_in[20];
    const float* g_b_out = (const float*)d_in[21];
    const float* conv_W  = (const float*)d_in[22];
    const float* conv_b  = (const float*)d_in[23];
    float* out = (float*)d_out;

    cudaFuncSetAttribute(k_agg, cudaFuncAttributeMaxDynamicSharedMemorySize, AGG_SMEM);
    cudaFuncSetAttribute(k_gz,  cudaFuncAttributeMaxDynamicSharedMemorySize, GZ_SMEM_TOT);

    for (int step = 0; step < NSTEP; step++){
        for (int stage = 0; stage < 4; stage++){
            int grid = (step==0 && stage==0) ? FG1_GRID_PRE : FG1_BLKS;
            k_fg1<<<grid, 64>>>(times, coeff_a, coeff_b, coeff_c, coeff_d,
                                h_W, h_b, z_W, z_b,
                                f_W_in, f_b_in, f_W_mid, f_b_mid, f_W_out, f_b_out,
                                g_W_in, g_b_in, g_E, g_bpool, g_Wpool, g_W_out,
                                step, stage);
            k_agg<<<dim3(10,8), 256, AGG_SMEM>>>();
            k_x2<<<dim3(Nn,2), 256>>>();
            k_gz<<<dim3(77,32), 256, GZ_SMEM_TOT>>>(g_b_out, stage);
        }
    }
    k_out<<<Rr, 64>>>(conv_W, conv_b, times, out);
}